// round 13
// baseline (speedup 1.0000x reference)
#include <cuda_runtime.h>
#include <cuda_bf16.h>
#include <math.h>

#define LSIG 65537
#define RS 273                 // per-FFT smem stride (float2), RS % 16 == 1
#define TWO_PI 6.283185307179586476925286766559

struct cx { float re, im; };

__device__ __forceinline__ cx cmul(cx a, cx b){
    cx r; r.re = a.re*b.re - a.im*b.im; r.im = a.re*b.im + a.im*b.re; return r;
}

// exp(sign * 2*pi*i * idx / 2^LOGN), sign = +1 if INV else -1.
template<int LOGN, bool INV>
__device__ __forceinline__ cx cisw(int idx){
    const int N = 1 << LOGN;
    int m = idx & (N - 1);
    if (m >= (N >> 1)) m -= N;
    const float k = (INV ? (float)TWO_PI : -(float)TWO_PI) / (float)N;
    float s, c;
    __sincosf(k * (float)m, &s, &c);
    cx r; r.re = c; r.im = s; return r;
}

// W16[m] = exp(-2*pi*i*m/16)
__device__ __constant__ float W16R[16] = {
    1.0f, 0.9238795325112867f, 0.7071067811865476f, 0.3826834323650898f,
    0.0f,-0.3826834323650898f,-0.7071067811865476f,-0.9238795325112867f,
   -1.0f,-0.9238795325112867f,-0.7071067811865476f,-0.3826834323650898f,
    0.0f, 0.3826834323650898f, 0.7071067811865476f, 0.9238795325112867f };
__device__ __constant__ float W16I[16] = {
    0.0f,-0.3826834323650898f,-0.7071067811865476f,-0.9238795325112867f,
   -1.0f,-0.9238795325112867f,-0.7071067811865476f,-0.3826834323650898f,
    0.0f, 0.3826834323650898f, 0.7071067811865476f, 0.9238795325112867f,
    1.0f, 0.9238795325112867f, 0.7071067811865476f, 0.3826834323650898f };

template<bool INV>
__device__ __forceinline__ cx tw16(int m){
    cx r; r.re = W16R[m]; r.im = INV ? -W16I[m] : W16I[m]; return r;
}

template<bool INV>
__device__ __forceinline__ void dft4(cx& x0, cx& x1, cx& x2, cx& x3){
    cx t0, t1, t2, t3;
    t0.re = x0.re + x2.re; t0.im = x0.im + x2.im;
    t1.re = x0.re - x2.re; t1.im = x0.im - x2.im;
    t2.re = x1.re + x3.re; t2.im = x1.im + x3.im;
    t3.re = x1.re - x3.re; t3.im = x1.im - x3.im;
    x0.re = t0.re + t2.re; x0.im = t0.im + t2.im;
    x2.re = t0.re - t2.re; x2.im = t0.im - t2.im;
    if (!INV){
        x1.re = t1.re + t3.im; x1.im = t1.im - t3.re;
        x3.re = t1.re - t3.im; x3.im = t1.im + t3.re;
    } else {
        x1.re = t1.re - t3.im; x1.im = t1.im + t3.re;
        x3.re = t1.re + t3.im; x3.im = t1.im - t3.re;
    }
}

// 16-pt DFT, natural in/out.
template<bool INV>
__device__ __forceinline__ void fft16(cx* v){
    cx u[16];
    #pragma unroll
    for (int b = 0; b < 4; b++){
        cx a0 = v[b], a1 = v[4+b], a2 = v[8+b], a3 = v[12+b];
        dft4<INV>(a0, a1, a2, a3);
        u[b]      = a0;
        u[4+b]    = cmul(a1, tw16<INV>(b));
        u[8+b]    = cmul(a2, tw16<INV>(2*b));
        u[12+b]   = cmul(a3, tw16<INV>(3*b));
    }
    #pragma unroll
    for (int k1 = 0; k1 < 4; k1++){
        cx a0 = u[k1*4+0], a1 = u[k1*4+1], a2 = u[k1*4+2], a3 = u[k1*4+3];
        dft4<INV>(a0, a1, a2, a3);
        v[k1] = a0; v[k1+4] = a1; v[k1+8] = a2; v[k1+12] = a3;
    }
}

// scratch: 2 x 256 signals x 65536 complex
__device__ float2 g_bufA[1u << 24];
__device__ float2 g_bufB[1u << 24];
__device__ float  g_gain[LSIG];
__device__ float2 g_twid[LSIG];     // exp(-i*pi*j/65536), j=0..65536
__device__ double g_pm_acc;

// ---- batched 256-pt FFT core: 16 FFTs per block, thread t: g=t>>4, lane=t&15
template<bool INV>
__device__ __forceinline__ void fft256_core(float2* S, int t, cx* w){
    int g = t >> 4, lane = t & 15;
    float2* B = S + g * RS;
    cx v[16];
    #pragma unroll
    for (int b = 0; b < 16; b++){ float2 f = B[b*17 + lane]; v[b].re = f.x; v[b].im = f.y; }
    fft16<INV>(v);
    cx s1 = cisw<8, INV>(lane);
    cx s2 = cmul(s1, s1);
    cx s4 = cmul(s2, s2);
    cx p0; p0.re = 1.f; p0.im = 0.f;
    cx p1 = s1, p2 = s2, p3 = cmul(s2, s1);
    __syncwarp();
    #pragma unroll
    for (int q = 0; q < 4; q++){
        cx r0 = cmul(v[4*q+0], p0);
        cx r1 = cmul(v[4*q+1], p1);
        cx r2 = cmul(v[4*q+2], p2);
        cx r3 = cmul(v[4*q+3], p3);
        B[lane*17 + 4*q+0] = make_float2(r0.re, r0.im);
        B[lane*17 + 4*q+1] = make_float2(r1.re, r1.im);
        B[lane*17 + 4*q+2] = make_float2(r2.re, r2.im);
        B[lane*17 + 4*q+3] = make_float2(r3.re, r3.im);
        if (q < 3){ p0 = cmul(p0, s4); p1 = cmul(p1, s4); p2 = cmul(p2, s4); p3 = cmul(p3, s4); }
    }
    __syncwarp();
    cx u[16];
    #pragma unroll
    for (int a = 0; a < 16; a++){ float2 f = B[a*17 + lane]; u[a].re = f.x; u[a].im = f.y; }
    fft16<INV>(u);
    #pragma unroll
    for (int d = 0; d < 16; d++) w[d] = u[d];
}

__device__ __forceinline__ void load_generic(const float2* __restrict__ src, float2* S, int t){
    int cl = t & 15, q = t >> 4;
    #pragma unroll
    for (int j = 0; j < 16; j++){
        int m = j*16 + q;
        float2 vv = src[m*256 + cl];
        S[cl*RS + j*17 + q] = vv;
    }
}

// output twiddle + store: dst[lane+16d] = w[d] * exp(sign*2pi*i*n1*(lane+16d)/65536)
template<bool INV>
__device__ __forceinline__ void store_twiddled(float2* dst, const cx* w, int n1, int lane){
    cx base = cisw<16, INV>(n1 * lane);
    cx st   = cisw<16, INV>(n1 * 16);
    cx st2  = cmul(st, st);
    cx st4  = cmul(st2, st2);
    cx u0 = base;
    cx u1 = cmul(base, st);
    cx u2 = cmul(base, st2);
    cx u3 = cmul(u1,  st2);
    #pragma unroll
    for (int q = 0; q < 4; q++){
        cx r0 = cmul(w[4*q+0], u0);
        cx r1 = cmul(w[4*q+1], u1);
        cx r2 = cmul(w[4*q+2], u2);
        cx r3 = cmul(w[4*q+3], u3);
        dst[lane + 16*(4*q+0)] = make_float2(r0.re, r0.im);
        dst[lane + 16*(4*q+1)] = make_float2(r1.re, r1.im);
        dst[lane + 16*(4*q+2)] = make_float2(r2.re, r2.im);
        dst[lane + 16*(4*q+3)] = make_float2(r3.re, r3.im);
        if (q < 3){ u0 = cmul(u0, st4); u1 = cmul(u1, st4); u2 = cmul(u2, st4); u3 = cmul(u3, st4); }
    }
}

// ---------------- init: twiddle table + pm accumulator zero ----------------
__global__ void k_init(){
    int j = blockIdx.x * 256 + threadIdx.x;
    if (j == 0) g_pm_acc = 0.0;
    if (j > 65536) return;
    float a = (float)(-(double)j * (3.14159265358979323846 / 65536.0));
    float s, c;
    sincosf(a, &s, &c);
    g_twid[j] = make_float2(c, s);
}

// ---------------- forward step 1: pack x -> z, column FFT, twiddle ----------------
__global__ void __launch_bounds__(256) k_f1(const float* __restrict__ x){
    __shared__ float2 S[16*RS];
    int t = threadIdx.x, base = blockIdx.x * 16, s = blockIdx.y;
    const float* xs = x + (size_t)s * LSIG;
    {
        int cl = t & 15, q = t >> 4;
        #pragma unroll
        for (int j = 0; j < 16; j++){
            int m = j*16 + q;
            int n = base + cl + 256*m;
            float2 vv;
            vv.x = (n <= 32768) ? xs[2*n]   : 0.f;
            vv.y = (n <= 32767) ? xs[2*n+1] : 0.f;
            S[cl*RS + j*17 + q] = vv;
        }
    }
    __syncthreads();
    cx w[16];
    fft256_core<false>(S, t, w);
    int g = t >> 4, lane = t & 15;
    int n1 = base + g;
    float2* dst = g_bufA + ((size_t)s << 16) + n1*256;
    store_twiddled<false>(dst, w, n1, lane);
}

// ---------------- forward step 2: row FFT, natural-order transpose out ----------------
__global__ void __launch_bounds__(256) k_f2(){
    __shared__ float2 S[16*RS];
    int t = threadIdx.x, base = blockIdx.x * 16, s = blockIdx.y;
    load_generic(g_bufA + ((size_t)s << 16) + base, S, t);
    __syncthreads();
    cx w[16];
    fft256_core<false>(S, t, w);
    int g = t >> 4, lane = t & 15;
    __syncthreads();
    #pragma unroll
    for (int d = 0; d < 16; d++)
        S[(lane + 16*d)*17 + g] = make_float2(w[d].re, w[d].im);
    __syncthreads();
    float2* dst = g_bufB + ((size_t)s << 16) + base;
    int kk = t & 15, q = t >> 4;
    #pragma unroll
    for (int r = 0; r < 16; r++){
        int k2 = r*16 + q;
        dst[k2*256 + kk] = S[k2*17 + kk];
    }
}

// ---------------- fused spectral + inverse step 1 ----------------
// Compute Xg[j] and Xg[65536-j] from one pair of Z loads (mirror algebra).
__device__ __forceinline__ void xg_pair(const float2* __restrict__ Z, int j, cx& lo, cx& hi){
    float2 za = Z[j & 65535];
    float2 zb = Z[(65536 - j) & 65535];
    float Ere = 0.5f*(za.x + zb.x), Eim = 0.5f*(za.y - zb.y);
    float Ore = 0.5f*(za.y + zb.y), Oim = -0.5f*(za.x - zb.x);
    float2 ph = g_twid[j];                 // exp(-i*pi*j/65536)
    float gl = g_gain[j];
    lo.re = (Ere + ph.x*Ore - ph.y*Oim) * gl;
    lo.im = (Eim + ph.x*Oim + ph.y*Ore) * gl;
    // mirror: E'=conj(E), O'=conj(O), ph' = -conj(ph)
    float gh = g_gain[65536 - j];
    hi.re = ( Ere - ph.x*Ore + ph.y*Oim) * gh;
    hi.im = (-Eim + ph.x*Oim + ph.y*Ore) * gh;
}

__device__ __forceinline__ float cmag(cx a){ return sqrtf(a.re*a.re + a.im*a.im); }

// Zs[K] (repacked smoothed spectrum) computed on the fly, valid for K in 0..65535.
__device__ __forceinline__ float2 zs_at(const float2* __restrict__ Z, int K){
    cx L[3], H[3];
    #pragma unroll
    for (int d = 0; d < 3; d++){
        int j = K - 1 + d;
        if (j >= 0){
            xg_pair(Z, j, L[d], H[d]);
        } else {
            L[d].re = L[d].im = 0.f; H[d].re = H[d].im = 0.f;
        }
    }
    float mgl = cmag(L[1]);
    float mgh = cmag(H[1]);
    float ms, msh;
    if (K == 0){            // k=0 and km=65536 are both spectrum edges
        ms  = mgl;
        msh = mgh;
    } else {
        ms  = 0.7f*mgl + 0.15f*cmag(L[0]) + 0.15f*cmag(L[2]);
        msh = 0.7f*mgh + 0.15f*cmag(H[0]) + 0.15f*cmag(H[2]);
    }
    cx xck, xcm;
    if (mgl > 0.f){ float sc = ms/mgl;  xck.re = L[1].re*sc; xck.im = L[1].im*sc; }
    else          { xck.re = ms;  xck.im = 0.f; }
    if (mgh > 0.f){ float sc = msh/mgh; xcm.re = H[1].re*sc; xcm.im = H[1].im*sc; }
    else          { xcm.re = msh; xcm.im = 0.f; }
    // repack: Zs[K] = E + i*O, O = 0.5*exp(+i*pi*K/65536)*(Xc[K]-conj(Xc[M-K]))
    float2 pht = g_twid[K];
    float Ere = 0.5f*(xck.re + xcm.re), Eim = 0.5f*(xck.im - xcm.im);
    float Dre = xck.re - xcm.re,        Dim = xck.im + xcm.im;
    float Ore = 0.5f*(pht.x*Dre + pht.y*Dim);
    float Oim = 0.5f*(pht.x*Dim - pht.y*Dre);
    return make_float2(Ere - Oim, Eim + Ore);
}

__global__ void __launch_bounds__(256) k_i1f(){
    __shared__ float2 S[16*RS];
    int t = threadIdx.x, base = blockIdx.x * 16, s = blockIdx.y;
    const float2* Z = g_bufB + ((size_t)s << 16);
    int cl = t & 15, q = t >> 4;
    #pragma unroll 2
    for (int j16 = 0; j16 < 16; j16++){
        int m = j16*16 + q;
        int K = m*256 + base + cl;
        S[cl*RS + j16*17 + q] = zs_at(Z, K);
    }
    __syncthreads();
    cx w[16];
    fft256_core<true>(S, t, w);
    int g = t >> 4, lane = t & 15;
    int c = base + g;
    float2* dst = g_bufA + ((size_t)s << 16) + c*256;
    store_twiddled<true>(dst, w, c, lane);
}

// ---------------- inverse step 2: inverse FFT over c, unpack z -> y ----------------
__global__ void __launch_bounds__(256) k_i2(float* __restrict__ y){
    __shared__ float2 S[16*RS];
    int t = threadIdx.x, base = blockIdx.x * 16, s = blockIdx.y;
    load_generic(g_bufA + ((size_t)s << 16) + base, S, t);
    __syncthreads();
    cx w[16];
    fft256_core<true>(S, t, w);
    int g = t >> 4, lane = t & 15;
    __syncthreads();
    #pragma unroll
    for (int d = 0; d < 16; d++)
        S[(lane + 16*d)*17 + g] = make_float2(w[d].re, w[d].im);
    __syncthreads();
    float* Y = y + (size_t)s * LSIG;
    int kk = t & 15, q = t >> 4;
    const float invM = 1.0f / 65536.0f;
    for (int r = 0; r < 9; r++){
        int n2 = r*16 + q;
        if (n2 > 128) continue;
        int n = base + kk + 256*n2;
        if (n > 32768) continue;
        float2 vv = S[n2*17 + kk];
        Y[2*n] = vv.x * invM;
        if (n <= 32767) Y[2*n + 1] = vv.y * invM;
    }
}

// ---------------- progression mean (parallel) ----------------
__global__ void k_pm(const float* __restrict__ hp, const float* __restrict__ b1,
                     const float* __restrict__ W2, const float* __restrict__ b2,
                     const float* __restrict__ W3, const float* __restrict__ b3){
    __shared__ float s_md;
    __shared__ float s_row[8];
    __shared__ double red[256];
    int t = threadIdx.x;
    if (t == 0){
        float h1[32], h2[16];
        for (int i = 0; i < 32; i++) h1[i] = fmaxf(b1[i], 0.f);
        for (int j = 0; j < 16; j++){
            float acc = b2[j];
            for (int i = 0; i < 32; i++) acc = fmaf(h1[i], W2[i*16 + j], acc);
            h2[j] = fmaxf(acc, 0.f);
        }
        float md = b3[1];
        for (int j = 0; j < 16; j++) md = fmaf(h2[j], W3[j*8 + 1], md);
        s_md = md;
    }
    if (t < 8) s_row[t] = hp[t*4] + hp[t*4+1] + hp[t*4+2] + hp[t*4+3];
    __syncthreads();
    double md = (double)s_md;
    double acc = 0.0;
    int stride = gridDim.x * 256;
    for (int i = blockIdx.x * 256 + t; i < LSIG; i += stride){
        int ci = (int)floorf((float)i * 8.0f / 65537.0f) & 7;
        double sf = sin(TWO_PI * (double)i / 65537.0);
        acc += (1.0 + md * sf) * (double)s_row[ci];
    }
    red[t] = acc;
    __syncthreads();
    for (int off = 128; off; off >>= 1){
        if (t < off) red[t] += red[t + off];
        __syncthreads();
    }
    if (t == 0) atomicAdd(&g_pm_acc, red[0]);
}

// ---------------- gain ----------------
struct GainP {
    int   hidx[40];
    float invm[5];
    float win[31];
};

__global__ void k_gain(const float* __restrict__ bw, const float* __restrict__ fw, GainP P){
    int i = blockIdx.x * 256 + threadIdx.x;
    if (i > 65536) return;
    const double df = 22050.0 / 131072.0;
    float fr = (float)((double)i * df);
    float g = 1.0f;
    const float lo[6] = {1.f, 4.f, 8.f, 13.f, 30.f, 100.f};
    const float hi[6] = {4.f, 8.f, 13.f, 30.f, 100.f, 200.f};
    #pragma unroll
    for (int kb = 0; kb < 6; kb++){
        float center = 0.5f*(lo[kb] + hi[kb]);
        float halfw  = 0.25f*(hi[kb] - lo[kb]);
        float m = 0.f;
        if (fr >= lo[kb] && fr <= hi[kb]){
            float dd = (fr - center) / halfw;
            m = expf(-0.5f * dd * dd);
        }
        float c1 = (float)(TWO_PI * (double)center);
        float tm = sinf(c1 * (float)i / 22050.0f);
        g = g * (1.0f + m * bw[kb] * (1.0f + 0.2f * tm));
    }
    float pm1 = 1.0f + (float)(g_pm_acc * (1.0 / (4.0 * 65537.0)));
    #pragma unroll
    for (int j = 0; j < 8; j++){
        float fwj = fw[j];
        #pragma unroll
        for (int mi = 0; mi < 5; mi++){
            int hidx = P.hidx[j*5 + mi];
            int d = i - hidx;
            if (d >= -15 && d <= 15){
                float enh = fwj * P.win[d + 15] * P.invm[mi] * pm1;
                g *= (1.0f + enh);
            }
        }
    }
    g_gain[i] = g;
}

extern "C" void kernel_launch(void* const* d_in, const int* in_sizes, int n_in,
                              void* d_out, int out_size){
    const float* x  = (const float*)d_in[0];
    const float* bw = (const float*)d_in[1];
    const float* fw = (const float*)d_in[2];
    const float* hp = (const float*)d_in[3];
    const float* b1 = (const float*)d_in[5];
    const float* W2 = (const float*)d_in[6];
    const float* b2 = (const float*)d_in[7];
    const float* W3 = (const float*)d_in[8];
    const float* b3 = (const float*)d_in[9];
    float* y = (float*)d_out;

    GainP P;
    {
        const double df = 22050.0 / 131072.0;
        const double fs[8] = {7.83, 528.0, 396.0, 2.5, 14.1, 432.0, 6.0, 30.0};
        for (int j = 0; j < 8; j++){
            for (int mi = 0; mi < 5; mi++){
                double hf = fs[j] * (double)(mi + 1);
                int i0 = (int)(hf / df);
                float fh = (float)hf;
                float fa = fabsf((float)((double)i0 * df) - fh);
                float fb = fabsf((float)((double)(i0 + 1) * df) - fh);
                P.hidx[j*5 + mi] = (fa <= fb) ? i0 : (i0 + 1);
            }
        }
        for (int mi = 0; mi < 5; mi++)
            P.invm[mi] = (float)(1.0 / pow((double)(mi + 1), 1.2));
        for (int d = 0; d < 31; d++){
            double dd = (double)(d - 15) / 5.0;
            P.win[d] = (float)exp(-0.5 * dd * dd);
        }
    }

    k_init<<<257, 256>>>();
    k_pm<<<64, 256>>>(hp, b1, W2, b2, W3, b3);
    k_gain<<<257, 256>>>(bw, fw, P);
    dim3 grid(16, 256);
    k_f1<<<grid, 256>>>(x);
    k_f2<<<grid, 256>>>();
    k_i1f<<<grid, 256>>>();
    k_i2<<<grid, 256>>>(y);
    (void)in_sizes; (void)n_in; (void)out_size;
}

// round 15
// speedup vs baseline: 1.2881x; 1.2881x over previous
#include <cuda_runtime.h>
#include <cuda_bf16.h>
#include <math.h>

#define LSIG 65537
#define RS 273                 // per-FFT smem stride (float2), RS % 16 == 1
#define TWO_PI 6.283185307179586476925286766559

struct cx { float re, im; };

__device__ __forceinline__ cx cmul(cx a, cx b){
    cx r; r.re = a.re*b.re - a.im*b.im; r.im = a.re*b.im + a.im*b.re; return r;
}

// exp(sign * 2*pi*i * idx / 2^LOGN), sign = +1 if INV else -1.
template<int LOGN, bool INV>
__device__ __forceinline__ cx cisw(int idx){
    const int N = 1 << LOGN;
    int m = idx & (N - 1);
    if (m >= (N >> 1)) m -= N;
    const float k = (INV ? (float)TWO_PI : -(float)TWO_PI) / (float)N;
    float s, c;
    __sincosf(k * (float)m, &s, &c);
    cx r; r.re = c; r.im = s; return r;
}

// W16[m] = exp(-2*pi*i*m/16)
__device__ __constant__ float W16R[16] = {
    1.0f, 0.9238795325112867f, 0.7071067811865476f, 0.3826834323650898f,
    0.0f,-0.3826834323650898f,-0.7071067811865476f,-0.9238795325112867f,
   -1.0f,-0.9238795325112867f,-0.7071067811865476f,-0.3826834323650898f,
    0.0f, 0.3826834323650898f, 0.7071067811865476f, 0.9238795325112867f };
__device__ __constant__ float W16I[16] = {
    0.0f,-0.3826834323650898f,-0.7071067811865476f,-0.9238795325112867f,
   -1.0f,-0.9238795325112867f,-0.7071067811865476f,-0.3826834323650898f,
    0.0f, 0.3826834323650898f, 0.7071067811865476f, 0.9238795325112867f,
    1.0f, 0.9238795325112867f, 0.7071067811865476f, 0.3826834323650898f };

template<bool INV>
__device__ __forceinline__ cx tw16(int m){
    cx r; r.re = W16R[m]; r.im = INV ? -W16I[m] : W16I[m]; return r;
}

template<bool INV>
__device__ __forceinline__ void dft4(cx& x0, cx& x1, cx& x2, cx& x3){
    cx t0, t1, t2, t3;
    t0.re = x0.re + x2.re; t0.im = x0.im + x2.im;
    t1.re = x0.re - x2.re; t1.im = x0.im - x2.im;
    t2.re = x1.re + x3.re; t2.im = x1.im + x3.im;
    t3.re = x1.re - x3.re; t3.im = x1.im - x3.im;
    x0.re = t0.re + t2.re; x0.im = t0.im + t2.im;
    x2.re = t0.re - t2.re; x2.im = t0.im - t2.im;
    if (!INV){
        x1.re = t1.re + t3.im; x1.im = t1.im - t3.re;
        x3.re = t1.re - t3.im; x3.im = t1.im + t3.re;
    } else {
        x1.re = t1.re - t3.im; x1.im = t1.im + t3.re;
        x3.re = t1.re + t3.im; x3.im = t1.im - t3.re;
    }
}

// 16-pt DFT, natural in/out.
template<bool INV>
__device__ __forceinline__ void fft16(cx* v){
    cx u[16];
    #pragma unroll
    for (int b = 0; b < 4; b++){
        cx a0 = v[b], a1 = v[4+b], a2 = v[8+b], a3 = v[12+b];
        dft4<INV>(a0, a1, a2, a3);
        u[b]      = a0;
        u[4+b]    = cmul(a1, tw16<INV>(b));
        u[8+b]    = cmul(a2, tw16<INV>(2*b));
        u[12+b]   = cmul(a3, tw16<INV>(3*b));
    }
    #pragma unroll
    for (int k1 = 0; k1 < 4; k1++){
        cx a0 = u[k1*4+0], a1 = u[k1*4+1], a2 = u[k1*4+2], a3 = u[k1*4+3];
        dft4<INV>(a0, a1, a2, a3);
        v[k1] = a0; v[k1+4] = a1; v[k1+8] = a2; v[k1+12] = a3;
    }
}

// scratch: 2 x 256 signals x 65536 complex
__device__ float2 g_bufA[1u << 24];
__device__ float2 g_bufB[1u << 24];
__device__ float  g_gain[LSIG];
__device__ float2 g_twid[LSIG];     // exp(-i*pi*j/65536), j=0..65536
__device__ double g_pm_acc;

// ---- batched 256-pt FFT core: 16 FFTs per block, thread t: g=t>>4, lane=t&15
template<bool INV>
__device__ __forceinline__ void fft256_core(float2* S, int t, cx* w){
    int g = t >> 4, lane = t & 15;
    float2* B = S + g * RS;
    cx v[16];
    #pragma unroll
    for (int b = 0; b < 16; b++){ float2 f = B[b*17 + lane]; v[b].re = f.x; v[b].im = f.y; }
    fft16<INV>(v);
    cx s1 = cisw<8, INV>(lane);
    cx s2 = cmul(s1, s1);
    cx s4 = cmul(s2, s2);
    cx p0; p0.re = 1.f; p0.im = 0.f;
    cx p1 = s1, p2 = s2, p3 = cmul(s2, s1);
    __syncwarp();
    #pragma unroll
    for (int q = 0; q < 4; q++){
        cx r0 = cmul(v[4*q+0], p0);
        cx r1 = cmul(v[4*q+1], p1);
        cx r2 = cmul(v[4*q+2], p2);
        cx r3 = cmul(v[4*q+3], p3);
        B[lane*17 + 4*q+0] = make_float2(r0.re, r0.im);
        B[lane*17 + 4*q+1] = make_float2(r1.re, r1.im);
        B[lane*17 + 4*q+2] = make_float2(r2.re, r2.im);
        B[lane*17 + 4*q+3] = make_float2(r3.re, r3.im);
        if (q < 3){ p0 = cmul(p0, s4); p1 = cmul(p1, s4); p2 = cmul(p2, s4); p3 = cmul(p3, s4); }
    }
    __syncwarp();
    cx u[16];
    #pragma unroll
    for (int a = 0; a < 16; a++){ float2 f = B[a*17 + lane]; u[a].re = f.x; u[a].im = f.y; }
    fft16<INV>(u);
    #pragma unroll
    for (int d = 0; d < 16; d++) w[d] = u[d];
}

__device__ __forceinline__ void load_generic(const float2* __restrict__ src, float2* S, int t){
    int cl = t & 15, q = t >> 4;
    #pragma unroll
    for (int j = 0; j < 16; j++){
        int m = j*16 + q;
        float2 vv = src[m*256 + cl];
        S[cl*RS + j*17 + q] = vv;
    }
}

// output twiddle + store: dst[lane+16d] = w[d] * exp(sign*2pi*i*n1*(lane+16d)/65536)
template<bool INV>
__device__ __forceinline__ void store_twiddled(float2* dst, const cx* w, int n1, int lane){
    cx base = cisw<16, INV>(n1 * lane);
    cx st   = cisw<16, INV>(n1 * 16);
    cx st2  = cmul(st, st);
    cx st4  = cmul(st2, st2);
    cx u0 = base;
    cx u1 = cmul(base, st);
    cx u2 = cmul(base, st2);
    cx u3 = cmul(u1,  st2);
    #pragma unroll
    for (int q = 0; q < 4; q++){
        cx r0 = cmul(w[4*q+0], u0);
        cx r1 = cmul(w[4*q+1], u1);
        cx r2 = cmul(w[4*q+2], u2);
        cx r3 = cmul(w[4*q+3], u3);
        dst[lane + 16*(4*q+0)] = make_float2(r0.re, r0.im);
        dst[lane + 16*(4*q+1)] = make_float2(r1.re, r1.im);
        dst[lane + 16*(4*q+2)] = make_float2(r2.re, r2.im);
        dst[lane + 16*(4*q+3)] = make_float2(r3.re, r3.im);
        if (q < 3){ u0 = cmul(u0, st4); u1 = cmul(u1, st4); u2 = cmul(u2, st4); u3 = cmul(u3, st4); }
    }
}

// ---------------- init: twiddle table + pm accumulator zero ----------------
__global__ void k_init(){
    int j = blockIdx.x * 256 + threadIdx.x;
    if (j == 0) g_pm_acc = 0.0;
    if (j > 65536) return;
    float a = (float)(-(double)j * (3.14159265358979323846 / 65536.0));
    float s, c;
    sincosf(a, &s, &c);
    g_twid[j] = make_float2(c, s);
}

// ---------------- forward step 1: pack x -> z, column FFT, twiddle ----------------
__global__ void __launch_bounds__(256) k_f1(const float* __restrict__ x){
    __shared__ float2 S[16*RS];
    int t = threadIdx.x, base = blockIdx.x * 16, s = blockIdx.y;
    const float* xs = x + (size_t)s * LSIG;
    {
        int cl = t & 15, q = t >> 4;
        #pragma unroll
        for (int j = 0; j < 16; j++){
            int m = j*16 + q;
            int n = base + cl + 256*m;
            float2 vv;
            vv.x = (n <= 32768) ? xs[2*n]   : 0.f;
            vv.y = (n <= 32767) ? xs[2*n+1] : 0.f;
            S[cl*RS + j*17 + q] = vv;
        }
    }
    __syncthreads();
    cx w[16];
    fft256_core<false>(S, t, w);
    int g = t >> 4, lane = t & 15;
    int n1 = base + g;
    float2* dst = g_bufA + ((size_t)s << 16) + n1*256;
    store_twiddled<false>(dst, w, n1, lane);
}

// ---------------- forward step 2: row FFT, natural-order transpose out ----------------
__global__ void __launch_bounds__(256) k_f2(){
    __shared__ float2 S[16*RS];
    int t = threadIdx.x, base = blockIdx.x * 16, s = blockIdx.y;
    load_generic(g_bufA + ((size_t)s << 16) + base, S, t);
    __syncthreads();
    cx w[16];
    fft256_core<false>(S, t, w);
    int g = t >> 4, lane = t & 15;
    __syncthreads();
    #pragma unroll
    for (int d = 0; d < 16; d++)
        S[(lane + 16*d)*17 + g] = make_float2(w[d].re, w[d].im);
    __syncthreads();
    float2* dst = g_bufB + ((size_t)s << 16) + base;
    int kk = t & 15, q = t >> 4;
    #pragma unroll
    for (int r = 0; r < 16; r++){
        int k2 = r*16 + q;
        dst[k2*256 + kk] = S[k2*17 + kk];
    }
}

// ---------------- spectral kernel (shared Z loads for bin + mirror) ----------------
__global__ void __launch_bounds__(256) k_spec(){
    __shared__ float2 sL[258]; __shared__ float mL[258];
    __shared__ float2 sH[258]; __shared__ float mH[258];
    int s = blockIdx.y;
    int t = threadIdx.x;
    int kb = blockIdx.x * 256;
    const float2* Z = g_bufB + ((size_t)s << 16);
    float2* W = g_bufA + ((size_t)s << 16);

    for (int i = t; i < 258; i += 256){
        int jL = kb - 1 + i;
        cx XL; XL.re = 0.f; XL.im = 0.f;
        cx XH; XH.re = 0.f; XH.im = 0.f;
        if (jL >= 0 && jL <= 65536){
            float2 za = Z[jL & 65535];
            float2 zb = Z[(65536 - jL) & 65535];
            float Ere = 0.5f*(za.x + zb.x), Eim = 0.5f*(za.y - zb.y);
            float Ore = 0.5f*(za.y + zb.y), Oim = -0.5f*(za.x - zb.x);
            float2 ph = g_twid[jL];
            float gl = g_gain[jL];
            XL.re = (Ere + ph.x*Ore - ph.y*Oim) * gl;
            XL.im = (Eim + ph.x*Oim + ph.y*Ore) * gl;
            // mirror jh = 65536 - jL: E'=conj(E), O'=conj(O), ph' = -conj(ph)
            float gh = g_gain[65536 - jL];
            XH.re = ( Ere - ph.x*Ore + ph.y*Oim) * gh;
            XH.im = (-Eim + ph.x*Oim + ph.y*Ore) * gh;
        }
        sL[i] = make_float2(XL.re, XL.im);
        mL[i] = sqrtf(XL.re*XL.re + XL.im*XL.im);
        sH[i] = make_float2(XH.re, XH.im);
        mH[i] = sqrtf(XH.re*XH.re + XH.im*XH.im);
    }
    __syncthreads();

    int k = kb + t;
    if (k > 32768) return;
    int km = 65536 - k;

    float2 xk = sL[t+1]; float mg = mL[t+1];
    float ms = (k == 0 || k == 65536) ? mg
             : 0.7f*mg + 0.15f*mL[t] + 0.15f*mL[t+2];
    cx xck;
    if (mg > 0.f){ float sc = ms/mg; xck.re = xk.x*sc; xck.im = xk.y*sc; }
    else         { xck.re = ms; xck.im = 0.f; }

    // sH[i] holds Xg(65536-(kb-1+i)) => for km: i = t+1; neighbors km-1 -> i=t+2, km+1 -> i=t
    float2 xh = sH[t+1]; float mgh = mH[t+1];
    float msh = (km == 0 || km == 65536) ? mgh
              : 0.7f*mgh + 0.15f*mH[t+2] + 0.15f*mH[t];
    cx xcm;
    if (mgh > 0.f){ float sc = msh/mgh; xcm.re = xh.x*sc; xcm.im = xh.y*sc; }
    else          { xcm.re = msh; xcm.im = 0.f; }

    float2 phc = g_twid[k];      // exp(-i*pi*k/65536); repack needs conj
    cx E, D, O;
    E.re = 0.5f*(xck.re + xcm.re); E.im = 0.5f*(xck.im - xcm.im);
    D.re = xck.re - xcm.re;        D.im = xck.im + xcm.im;
    O.re = 0.5f*(phc.x*D.re + phc.y*D.im);
    O.im = 0.5f*(phc.x*D.im - phc.y*D.re);
    W[k] = make_float2(E.re - O.im, E.im + O.re);
    if (k >= 1 && k <= 32767)
        W[km] = make_float2(E.re + O.im, O.re - E.im);
}

// ---------------- inverse step 1 ----------------
__global__ void __launch_bounds__(256) k_i1(){
    __shared__ float2 S[16*RS];
    int t = threadIdx.x, base = blockIdx.x * 16, s = blockIdx.y;
    load_generic(g_bufA + ((size_t)s << 16) + base, S, t);
    __syncthreads();
    cx w[16];
    fft256_core<true>(S, t, w);
    int g = t >> 4, lane = t & 15;
    int c = base + g;
    float2* dst = g_bufB + ((size_t)s << 16) + c*256;
    store_twiddled<true>(dst, w, c, lane);
}

// ---------------- inverse step 2: inverse FFT over c, unpack z -> y ----------------
__global__ void __launch_bounds__(256) k_i2(float* __restrict__ y){
    __shared__ float2 S[16*RS];
    int t = threadIdx.x, base = blockIdx.x * 16, s = blockIdx.y;
    load_generic(g_bufB + ((size_t)s << 16) + base, S, t);
    __syncthreads();
    cx w[16];
    fft256_core<true>(S, t, w);
    int g = t >> 4, lane = t & 15;
    __syncthreads();
    #pragma unroll
    for (int d = 0; d < 16; d++)
        S[(lane + 16*d)*17 + g] = make_float2(w[d].re, w[d].im);
    __syncthreads();
    float* Y = y + (size_t)s * LSIG;
    int kk = t & 15, q = t >> 4;
    const float invM = 1.0f / 65536.0f;
    for (int r = 0; r < 9; r++){
        int n2 = r*16 + q;
        if (n2 > 128) continue;
        int n = base + kk + 256*n2;
        if (n > 32768) continue;
        float2 vv = S[n2*17 + kk];
        Y[2*n] = vv.x * invM;
        if (n <= 32767) Y[2*n + 1] = vv.y * invM;
    }
}

// ---------------- progression mean (parallel) ----------------
__global__ void k_pm(const float* __restrict__ hp, const float* __restrict__ b1,
                     const float* __restrict__ W2, const float* __restrict__ b2,
                     const float* __restrict__ W3, const float* __restrict__ b3){
    __shared__ float s_md;
    __shared__ float s_row[8];
    __shared__ double red[256];
    int t = threadIdx.x;
    if (t == 0){
        float h1[32], h2[16];
        for (int i = 0; i < 32; i++) h1[i] = fmaxf(b1[i], 0.f);
        for (int j = 0; j < 16; j++){
            float acc = b2[j];
            for (int i = 0; i < 32; i++) acc = fmaf(h1[i], W2[i*16 + j], acc);
            h2[j] = fmaxf(acc, 0.f);
        }
        float md = b3[1];
        for (int j = 0; j < 16; j++) md = fmaf(h2[j], W3[j*8 + 1], md);
        s_md = md;
    }
    if (t < 8) s_row[t] = hp[t*4] + hp[t*4+1] + hp[t*4+2] + hp[t*4+3];
    __syncthreads();
    double md = (double)s_md;
    double acc = 0.0;
    int stride = gridDim.x * 256;
    for (int i = blockIdx.x * 256 + t; i < LSIG; i += stride){
        int ci = (int)floorf((float)i * 8.0f / 65537.0f) & 7;
        double sf = sin(TWO_PI * (double)i / 65537.0);
        acc += (1.0 + md * sf) * (double)s_row[ci];
    }
    red[t] = acc;
    __syncthreads();
    for (int off = 128; off; off >>= 1){
        if (t < off) red[t] += red[t + off];
        __syncthreads();
    }
    if (t == 0) atomicAdd(&g_pm_acc, red[0]);
}

// ---------------- gain ----------------
struct GainP {
    int   hidx[40];
    float invm[5];
    float win[31];
};

__global__ void k_gain(const float* __restrict__ bw, const float* __restrict__ fw, GainP P){
    int i = blockIdx.x * 256 + threadIdx.x;
    if (i > 65536) return;
    const double df = 22050.0 / 131072.0;
    float fr = (float)((double)i * df);
    float g = 1.0f;
    const float lo[6] = {1.f, 4.f, 8.f, 13.f, 30.f, 100.f};
    const float hi[6] = {4.f, 8.f, 13.f, 30.f, 100.f, 200.f};
    #pragma unroll
    for (int kb = 0; kb < 6; kb++){
        float center = 0.5f*(lo[kb] + hi[kb]);
        float halfw  = 0.25f*(hi[kb] - lo[kb]);
        float m = 0.f;
        if (fr >= lo[kb] && fr <= hi[kb]){
            float dd = (fr - center) / halfw;
            m = expf(-0.5f * dd * dd);
        }
        float c1 = (float)(TWO_PI * (double)center);
        float tm = sinf(c1 * (float)i / 22050.0f);
        g = g * (1.0f + m * bw[kb] * (1.0f + 0.2f * tm));
    }
    float pm1 = 1.0f + (float)(g_pm_acc * (1.0 / (4.0 * 65537.0)));
    #pragma unroll
    for (int j = 0; j < 8; j++){
        float fwj = fw[j];
        #pragma unroll
        for (int mi = 0; mi < 5; mi++){
            int hidx = P.hidx[j*5 + mi];
            int d = i - hidx;
            if (d >= -15 && d <= 15){
                float enh = fwj * P.win[d + 15] * P.invm[mi] * pm1;
                g *= (1.0f + enh);
            }
        }
    }
    g_gain[i] = g;
}

extern "C" void kernel_launch(void* const* d_in, const int* in_sizes, int n_in,
                              void* d_out, int out_size){
    const float* x  = (const float*)d_in[0];
    const float* bw = (const float*)d_in[1];
    const float* fw = (const float*)d_in[2];
    const float* hp = (const float*)d_in[3];
    const float* b1 = (const float*)d_in[5];
    const float* W2 = (const float*)d_in[6];
    const float* b2 = (const float*)d_in[7];
    const float* W3 = (const float*)d_in[8];
    const float* b3 = (const float*)d_in[9];
    float* y = (float*)d_out;

    GainP P;
    {
        const double df = 22050.0 / 131072.0;
        const double fs[8] = {7.83, 528.0, 396.0, 2.5, 14.1, 432.0, 6.0, 30.0};
        for (int j = 0; j < 8; j++){
            for (int mi = 0; mi < 5; mi++){
                double hf = fs[j] * (double)(mi + 1);
                int i0 = (int)(hf / df);
                float fh = (float)hf;
                float fa = fabsf((float)((double)i0 * df) - fh);
                float fb = fabsf((float)((double)(i0 + 1) * df) - fh);
                P.hidx[j*5 + mi] = (fa <= fb) ? i0 : (i0 + 1);
            }
        }
        for (int mi = 0; mi < 5; mi++)
            P.invm[mi] = (float)(1.0 / pow((double)(mi + 1), 1.2));
        for (int d = 0; d < 31; d++){
            double dd = (double)(d - 15) / 5.0;
            P.win[d] = (float)exp(-0.5 * dd * dd);
        }
    }

    k_init<<<257, 256>>>();
    k_pm<<<64, 256>>>(hp, b1, W2, b2, W3, b3);
    k_gain<<<257, 256>>>(bw, fw, P);
    dim3 grid(16, 256);
    k_f1<<<grid, 256>>>(x);
    k_f2<<<grid, 256>>>();
    k_spec<<<dim3(129, 256), 256>>>();
    k_i1<<<grid, 256>>>();
    k_i2<<<grid, 256>>>(y);
    (void)in_sizes; (void)n_in; (void)out_size;
}

// round 17
// speedup vs baseline: 1.3375x; 1.0384x over previous
#include <cuda_runtime.h>
#include <cuda_bf16.h>
#include <math.h>

#define LSIG 65537
#define RS 273                 // per-FFT smem stride (float2), RS % 16 == 1
#define TWO_PI 6.283185307179586476925286766559

struct cx { float re, im; };

__device__ __forceinline__ cx cmul(cx a, cx b){
    cx r; r.re = a.re*b.re - a.im*b.im; r.im = a.re*b.im + a.im*b.re; return r;
}

// exp(sign * 2*pi*i * idx / 2^LOGN), sign = +1 if INV else -1.
template<int LOGN, bool INV>
__device__ __forceinline__ cx cisw(int idx){
    const int N = 1 << LOGN;
    int m = idx & (N - 1);
    if (m >= (N >> 1)) m -= N;
    const float k = (INV ? (float)TWO_PI : -(float)TWO_PI) / (float)N;
    float s, c;
    __sincosf(k * (float)m, &s, &c);
    cx r; r.re = c; r.im = s; return r;
}

// W16[m] = exp(-2*pi*i*m/16)
__device__ __constant__ float W16R[16] = {
    1.0f, 0.9238795325112867f, 0.7071067811865476f, 0.3826834323650898f,
    0.0f,-0.3826834323650898f,-0.7071067811865476f,-0.9238795325112867f,
   -1.0f,-0.9238795325112867f,-0.7071067811865476f,-0.3826834323650898f,
    0.0f, 0.3826834323650898f, 0.7071067811865476f, 0.9238795325112867f };
__device__ __constant__ float W16I[16] = {
    0.0f,-0.3826834323650898f,-0.7071067811865476f,-0.9238795325112867f,
   -1.0f,-0.9238795325112867f,-0.7071067811865476f,-0.3826834323650898f,
    0.0f, 0.3826834323650898f, 0.7071067811865476f, 0.9238795325112867f,
    1.0f, 0.9238795325112867f, 0.7071067811865476f, 0.3826834323650898f };

template<bool INV>
__device__ __forceinline__ cx tw16(int m){
    cx r; r.re = W16R[m]; r.im = INV ? -W16I[m] : W16I[m]; return r;
}

template<bool INV>
__device__ __forceinline__ void dft4(cx& x0, cx& x1, cx& x2, cx& x3){
    cx t0, t1, t2, t3;
    t0.re = x0.re + x2.re; t0.im = x0.im + x2.im;
    t1.re = x0.re - x2.re; t1.im = x0.im - x2.im;
    t2.re = x1.re + x3.re; t2.im = x1.im + x3.im;
    t3.re = x1.re - x3.re; t3.im = x1.im - x3.im;
    x0.re = t0.re + t2.re; x0.im = t0.im + t2.im;
    x2.re = t0.re - t2.re; x2.im = t0.im - t2.im;
    if (!INV){
        x1.re = t1.re + t3.im; x1.im = t1.im - t3.re;
        x3.re = t1.re - t3.im; x3.im = t1.im + t3.re;
    } else {
        x1.re = t1.re - t3.im; x1.im = t1.im + t3.re;
        x3.re = t1.re + t3.im; x3.im = t1.im - t3.re;
    }
}

// 16-pt DFT, natural in/out.
template<bool INV>
__device__ __forceinline__ void fft16(cx* v){
    cx u[16];
    #pragma unroll
    for (int b = 0; b < 4; b++){
        cx a0 = v[b], a1 = v[4+b], a2 = v[8+b], a3 = v[12+b];
        dft4<INV>(a0, a1, a2, a3);
        u[b]      = a0;
        u[4+b]    = cmul(a1, tw16<INV>(b));
        u[8+b]    = cmul(a2, tw16<INV>(2*b));
        u[12+b]   = cmul(a3, tw16<INV>(3*b));
    }
    #pragma unroll
    for (int k1 = 0; k1 < 4; k1++){
        cx a0 = u[k1*4+0], a1 = u[k1*4+1], a2 = u[k1*4+2], a3 = u[k1*4+3];
        dft4<INV>(a0, a1, a2, a3);
        v[k1] = a0; v[k1+4] = a1; v[k1+8] = a2; v[k1+12] = a3;
    }
}

// scratch: 2 x 256 signals x 65536 complex
__device__ float2 g_bufA[1u << 24];
__device__ float2 g_bufB[1u << 24];
__device__ float  g_gain[LSIG];
__device__ float2 g_twid[LSIG];     // exp(-i*pi*j/65536), j=0..65536
__device__ double g_pm_acc;

// ---- batched 256-pt FFT core: 16 FFTs per block, thread t: g=t>>4, lane=t&15
template<bool INV>
__device__ __forceinline__ void fft256_core(float2* S, int t, cx* w){
    int g = t >> 4, lane = t & 15;
    float2* B = S + g * RS;
    cx v[16];
    #pragma unroll
    for (int b = 0; b < 16; b++){ float2 f = B[b*17 + lane]; v[b].re = f.x; v[b].im = f.y; }
    fft16<INV>(v);
    cx s1 = cisw<8, INV>(lane);
    cx s2 = cmul(s1, s1);
    cx s4 = cmul(s2, s2);
    cx p0; p0.re = 1.f; p0.im = 0.f;
    cx p1 = s1, p2 = s2, p3 = cmul(s2, s1);
    __syncwarp();
    #pragma unroll
    for (int q = 0; q < 4; q++){
        cx r0 = cmul(v[4*q+0], p0);
        cx r1 = cmul(v[4*q+1], p1);
        cx r2 = cmul(v[4*q+2], p2);
        cx r3 = cmul(v[4*q+3], p3);
        B[lane*17 + 4*q+0] = make_float2(r0.re, r0.im);
        B[lane*17 + 4*q+1] = make_float2(r1.re, r1.im);
        B[lane*17 + 4*q+2] = make_float2(r2.re, r2.im);
        B[lane*17 + 4*q+3] = make_float2(r3.re, r3.im);
        if (q < 3){ p0 = cmul(p0, s4); p1 = cmul(p1, s4); p2 = cmul(p2, s4); p3 = cmul(p3, s4); }
    }
    __syncwarp();
    cx u[16];
    #pragma unroll
    for (int a = 0; a < 16; a++){ float2 f = B[a*17 + lane]; u[a].re = f.x; u[a].im = f.y; }
    fft16<INV>(u);
    #pragma unroll
    for (int d = 0; d < 16; d++) w[d] = u[d];
}

__device__ __forceinline__ void load_generic(const float2* __restrict__ src, float2* S, int t){
    int cl = t & 15, q = t >> 4;
    #pragma unroll
    for (int j = 0; j < 16; j++){
        int m = j*16 + q;
        float2 vv = src[m*256 + cl];
        S[cl*RS + j*17 + q] = vv;
    }
}

// output twiddle + store: dst[lane+16d] = w[d] * exp(sign*2pi*i*n1*(lane+16d)/65536)
template<bool INV>
__device__ __forceinline__ void store_twiddled(float2* dst, const cx* w, int n1, int lane){
    cx base = cisw<16, INV>(n1 * lane);
    cx st   = cisw<16, INV>(n1 * 16);
    cx st2  = cmul(st, st);
    cx st4  = cmul(st2, st2);
    cx u0 = base;
    cx u1 = cmul(base, st);
    cx u2 = cmul(base, st2);
    cx u3 = cmul(u1,  st2);
    #pragma unroll
    for (int q = 0; q < 4; q++){
        cx r0 = cmul(w[4*q+0], u0);
        cx r1 = cmul(w[4*q+1], u1);
        cx r2 = cmul(w[4*q+2], u2);
        cx r3 = cmul(w[4*q+3], u3);
        dst[lane + 16*(4*q+0)] = make_float2(r0.re, r0.im);
        dst[lane + 16*(4*q+1)] = make_float2(r1.re, r1.im);
        dst[lane + 16*(4*q+2)] = make_float2(r2.re, r2.im);
        dst[lane + 16*(4*q+3)] = make_float2(r3.re, r3.im);
        if (q < 3){ u0 = cmul(u0, st4); u1 = cmul(u1, st4); u2 = cmul(u2, st4); u3 = cmul(u3, st4); }
    }
}

// ---------------- init: twiddle table + pm accumulator zero ----------------
__global__ void k_init(){
    int j = blockIdx.x * 256 + threadIdx.x;
    if (j == 0) g_pm_acc = 0.0;
    if (j > 65536) return;
    float a = (float)(-(double)j * (3.14159265358979323846 / 65536.0));
    float s, c;
    sincosf(a, &s, &c);
    g_twid[j] = make_float2(c, s);
}

// ---------------- forward step 1: pack x -> z, column FFT, twiddle ----------------
// processes signals in ASCENDING order (s = blockIdx.y)
__global__ void __launch_bounds__(256) k_f1(const float* __restrict__ x){
    __shared__ float2 S[16*RS];
    int t = threadIdx.x, base = blockIdx.x * 16, s = blockIdx.y;
    const float* xs = x + (size_t)s * LSIG;
    {
        int cl = t & 15, q = t >> 4;
        #pragma unroll
        for (int j = 0; j < 16; j++){
            int m = j*16 + q;
            int n = base + cl + 256*m;
            float2 vv;
            vv.x = (n <= 32768) ? xs[2*n]   : 0.f;
            vv.y = (n <= 32767) ? xs[2*n+1] : 0.f;
            S[cl*RS + j*17 + q] = vv;
        }
    }
    __syncthreads();
    cx w[16];
    fft256_core<false>(S, t, w);
    int g = t >> 4, lane = t & 15;
    int n1 = base + g;
    float2* dst = g_bufA + ((size_t)s << 16) + n1*256;
    store_twiddled<false>(dst, w, n1, lane);
}

// ---------------- forward step 2: row FFT, natural-order transpose out ----------------
// DESCENDING signal order: reads bufA tail (still L2-resident from f1),
// and finishes with bufB s=0..60 resident for k_spec's ascending reads.
__global__ void __launch_bounds__(256) k_f2(){
    __shared__ float2 S[16*RS];
    int t = threadIdx.x, base = blockIdx.x * 16, s = 255 - blockIdx.y;
    load_generic(g_bufA + ((size_t)s << 16) + base, S, t);
    __syncthreads();
    cx w[16];
    fft256_core<false>(S, t, w);
    int g = t >> 4, lane = t & 15;
    __syncthreads();
    #pragma unroll
    for (int d = 0; d < 16; d++)
        S[(lane + 16*d)*17 + g] = make_float2(w[d].re, w[d].im);
    __syncthreads();
    float2* dst = g_bufB + ((size_t)s << 16) + base;
    int kk = t & 15, q = t >> 4;
    #pragma unroll
    for (int r = 0; r < 16; r++){
        int k2 = r*16 + q;
        dst[k2*256 + kk] = S[k2*17 + kk];
    }
}

// ---------------- spectral kernel (shared Z loads for bin + mirror) ----------------
// ASCENDING signal order (matches f2's descending tail).
__global__ void __launch_bounds__(256) k_spec(){
    __shared__ float2 sL[258]; __shared__ float mL[258];
    __shared__ float2 sH[258]; __shared__ float mH[258];
    int s = blockIdx.y;
    int t = threadIdx.x;
    int kb = blockIdx.x * 256;
    const float2* Z = g_bufB + ((size_t)s << 16);
    float2* W = g_bufA + ((size_t)s << 16);

    for (int i = t; i < 258; i += 256){
        int jL = kb - 1 + i;
        cx XL; XL.re = 0.f; XL.im = 0.f;
        cx XH; XH.re = 0.f; XH.im = 0.f;
        if (jL >= 0 && jL <= 65536){
            float2 za = Z[jL & 65535];
            float2 zb = Z[(65536 - jL) & 65535];
            float Ere = 0.5f*(za.x + zb.x), Eim = 0.5f*(za.y - zb.y);
            float Ore = 0.5f*(za.y + zb.y), Oim = -0.5f*(za.x - zb.x);
            float2 ph = g_twid[jL];
            float gl = g_gain[jL];
            XL.re = (Ere + ph.x*Ore - ph.y*Oim) * gl;
            XL.im = (Eim + ph.x*Oim + ph.y*Ore) * gl;
            // mirror jh = 65536 - jL: E'=conj(E), O'=conj(O), ph' = -conj(ph)
            float gh = g_gain[65536 - jL];
            XH.re = ( Ere - ph.x*Ore + ph.y*Oim) * gh;
            XH.im = (-Eim + ph.x*Oim + ph.y*Ore) * gh;
        }
        sL[i] = make_float2(XL.re, XL.im);
        mL[i] = sqrtf(XL.re*XL.re + XL.im*XL.im);
        sH[i] = make_float2(XH.re, XH.im);
        mH[i] = sqrtf(XH.re*XH.re + XH.im*XH.im);
    }
    __syncthreads();

    int k = kb + t;
    if (k > 32768) return;
    int km = 65536 - k;

    float2 xk = sL[t+1]; float mg = mL[t+1];
    float ms = (k == 0 || k == 65536) ? mg
             : 0.7f*mg + 0.15f*mL[t] + 0.15f*mL[t+2];
    cx xck;
    if (mg > 0.f){ float sc = ms/mg; xck.re = xk.x*sc; xck.im = xk.y*sc; }
    else         { xck.re = ms; xck.im = 0.f; }

    // sH[i] holds Xg(65536-(kb-1+i)) => for km: i = t+1; neighbors km-1 -> i=t+2, km+1 -> i=t
    float2 xh = sH[t+1]; float mgh = mH[t+1];
    float msh = (km == 0 || km == 65536) ? mgh
              : 0.7f*mgh + 0.15f*mH[t+2] + 0.15f*mH[t];
    cx xcm;
    if (mgh > 0.f){ float sc = msh/mgh; xcm.re = xh.x*sc; xcm.im = xh.y*sc; }
    else          { xcm.re = msh; xcm.im = 0.f; }

    float2 phc = g_twid[k];      // exp(-i*pi*k/65536); repack needs conj
    cx E, D, O;
    E.re = 0.5f*(xck.re + xcm.re); E.im = 0.5f*(xck.im - xcm.im);
    D.re = xck.re - xcm.re;        D.im = xck.im + xcm.im;
    O.re = 0.5f*(phc.x*D.re + phc.y*D.im);
    O.im = 0.5f*(phc.x*D.im - phc.y*D.re);
    W[k] = make_float2(E.re - O.im, E.im + O.re);
    if (k >= 1 && k <= 32767)
        W[km] = make_float2(E.re + O.im, O.re - E.im);
}

// ---------------- inverse step 1 ----------------
// DESCENDING signal order (matches spec's ascending tail; leaves bufB head for i2).
__global__ void __launch_bounds__(256) k_i1(){
    __shared__ float2 S[16*RS];
    int t = threadIdx.x, base = blockIdx.x * 16, s = 255 - blockIdx.y;
    load_generic(g_bufA + ((size_t)s << 16) + base, S, t);
    __syncthreads();
    cx w[16];
    fft256_core<true>(S, t, w);
    int g = t >> 4, lane = t & 15;
    int c = base + g;
    float2* dst = g_bufB + ((size_t)s << 16) + c*256;
    store_twiddled<true>(dst, w, c, lane);
}

// ---------------- inverse step 2: inverse FFT over c, unpack z -> y ----------------
// ASCENDING signal order.
__global__ void __launch_bounds__(256) k_i2(float* __restrict__ y){
    __shared__ float2 S[16*RS];
    int t = threadIdx.x, base = blockIdx.x * 16, s = blockIdx.y;
    load_generic(g_bufB + ((size_t)s << 16) + base, S, t);
    __syncthreads();
    cx w[16];
    fft256_core<true>(S, t, w);
    int g = t >> 4, lane = t & 15;
    __syncthreads();
    #pragma unroll
    for (int d = 0; d < 16; d++)
        S[(lane + 16*d)*17 + g] = make_float2(w[d].re, w[d].im);
    __syncthreads();
    float* Y = y + (size_t)s * LSIG;
    int kk = t & 15, q = t >> 4;
    const float invM = 1.0f / 65536.0f;
    for (int r = 0; r < 9; r++){
        int n2 = r*16 + q;
        if (n2 > 128) continue;
        int n = base + kk + 256*n2;
        if (n > 32768) continue;
        float2 vv = S[n2*17 + kk];
        Y[2*n] = vv.x * invM;
        if (n <= 32767) Y[2*n + 1] = vv.y * invM;
    }
}

// ---------------- progression mean (parallel) ----------------
__global__ void k_pm(const float* __restrict__ hp, const float* __restrict__ b1,
                     const float* __restrict__ W2, const float* __restrict__ b2,
                     const float* __restrict__ W3, const float* __restrict__ b3){
    __shared__ float s_md;
    __shared__ float s_row[8];
    __shared__ double red[256];
    int t = threadIdx.x;
    if (t == 0){
        float h1[32], h2[16];
        for (int i = 0; i < 32; i++) h1[i] = fmaxf(b1[i], 0.f);
        for (int j = 0; j < 16; j++){
            float acc = b2[j];
            for (int i = 0; i < 32; i++) acc = fmaf(h1[i], W2[i*16 + j], acc);
            h2[j] = fmaxf(acc, 0.f);
        }
        float md = b3[1];
        for (int j = 0; j < 16; j++) md = fmaf(h2[j], W3[j*8 + 1], md);
        s_md = md;
    }
    if (t < 8) s_row[t] = hp[t*4] + hp[t*4+1] + hp[t*4+2] + hp[t*4+3];
    __syncthreads();
    double md = (double)s_md;
    double acc = 0.0;
    int stride = gridDim.x * 256;
    for (int i = blockIdx.x * 256 + t; i < LSIG; i += stride){
        int ci = (int)floorf((float)i * 8.0f / 65537.0f) & 7;
        double sf = sin(TWO_PI * (double)i / 65537.0);
        acc += (1.0 + md * sf) * (double)s_row[ci];
    }
    red[t] = acc;
    __syncthreads();
    for (int off = 128; off; off >>= 1){
        if (t < off) red[t] += red[t + off];
        __syncthreads();
    }
    if (t == 0) atomicAdd(&g_pm_acc, red[0]);
}

// ---------------- gain ----------------
struct GainP {
    int   hidx[40];
    float invm[5];
    float win[31];
};

__global__ void k_gain(const float* __restrict__ bw, const float* __restrict__ fw, GainP P){
    int i = blockIdx.x * 256 + threadIdx.x;
    if (i > 65536) return;
    const double df = 22050.0 / 131072.0;
    float fr = (float)((double)i * df);
    float g = 1.0f;
    const float lo[6] = {1.f, 4.f, 8.f, 13.f, 30.f, 100.f};
    const float hi[6] = {4.f, 8.f, 13.f, 30.f, 100.f, 200.f};
    #pragma unroll
    for (int kb = 0; kb < 6; kb++){
        float center = 0.5f*(lo[kb] + hi[kb]);
        float halfw  = 0.25f*(hi[kb] - lo[kb]);
        float m = 0.f;
        if (fr >= lo[kb] && fr <= hi[kb]){
            float dd = (fr - center) / halfw;
            m = expf(-0.5f * dd * dd);
        }
        float c1 = (float)(TWO_PI * (double)center);
        float tm = sinf(c1 * (float)i / 22050.0f);
        g = g * (1.0f + m * bw[kb] * (1.0f + 0.2f * tm));
    }
    float pm1 = 1.0f + (float)(g_pm_acc * (1.0 / (4.0 * 65537.0)));
    #pragma unroll
    for (int j = 0; j < 8; j++){
        float fwj = fw[j];
        #pragma unroll
        for (int mi = 0; mi < 5; mi++){
            int hidx = P.hidx[j*5 + mi];
            int d = i - hidx;
            if (d >= -15 && d <= 15){
                float enh = fwj * P.win[d + 15] * P.invm[mi] * pm1;
                g *= (1.0f + enh);
            }
        }
    }
    g_gain[i] = g;
}

extern "C" void kernel_launch(void* const* d_in, const int* in_sizes, int n_in,
                              void* d_out, int out_size){
    const float* x  = (const float*)d_in[0];
    const float* bw = (const float*)d_in[1];
    const float* fw = (const float*)d_in[2];
    const float* hp = (const float*)d_in[3];
    const float* b1 = (const float*)d_in[5];
    const float* W2 = (const float*)d_in[6];
    const float* b2 = (const float*)d_in[7];
    const float* W3 = (const float*)d_in[8];
    const float* b3 = (const float*)d_in[9];
    float* y = (float*)d_out;

    GainP P;
    {
        const double df = 22050.0 / 131072.0;
        const double fs[8] = {7.83, 528.0, 396.0, 2.5, 14.1, 432.0, 6.0, 30.0};
        for (int j = 0; j < 8; j++){
            for (int mi = 0; mi < 5; mi++){
                double hf = fs[j] * (double)(mi + 1);
                int i0 = (int)(hf / df);
                float fh = (float)hf;
                float fa = fabsf((float)((double)i0 * df) - fh);
                float fb = fabsf((float)((double)(i0 + 1) * df) - fh);
                P.hidx[j*5 + mi] = (fa <= fb) ? i0 : (i0 + 1);
            }
        }
        for (int mi = 0; mi < 5; mi++)
            P.invm[mi] = (float)(1.0 / pow((double)(mi + 1), 1.2));
        for (int d = 0; d < 31; d++){
            double dd = (double)(d - 15) / 5.0;
            P.win[d] = (float)exp(-0.5 * dd * dd);
        }
    }

    k_init<<<257, 256>>>();
    k_pm<<<64, 256>>>(hp, b1, W2, b2, W3, b3);
    k_gain<<<257, 256>>>(bw, fw, P);
    dim3 grid(16, 256);
    k_f1<<<grid, 256>>>(x);
    k_f2<<<grid, 256>>>();
    k_spec<<<dim3(129, 256), 256>>>();
    k_i1<<<grid, 256>>>();
    k_i2<<<grid, 256>>>(y);
    (void)in_sizes; (void)n_in; (void)out_size;
}